// round 7
// baseline (speedup 1.0000x reference)
#include <cuda_runtime.h>
#include <cuda_bf16.h>
#include <cstddef>

// ---------------------------------------------------------------------------
// DRNN: 2-layer SimpleRNN (tanh), B=512, T=512, D=64, H=100.
//   h1_t = tanh(x_t @ W1x + h1_{t-1} @ W1h + b1)
//   h2_t = tanh(h1_t @ W2x + h2_{t-1} @ W2h + b2)
//   out  = h2_T @ Wo + bo
// d_out: out[512] | h1_T[512*100] | h2_T[512*100]
//
// R4 data: 2 warps/SMSP was latency-bound (issue 33.6%). This version: 512
// threads (4 warps/SMSP), j-slice assigned per WARP so every h-state load is
// a warp-uniform broadcast LDS.128 (1 wavefront). Thread owns 1 hidden unit;
// recurrent weights live in registers (39 packed f32x2). Cross-slice
// reduction through SMEM with warp-contiguous access. 4 barriers/step.
// ---------------------------------------------------------------------------

#define T_STEPS 512
#define BATCH   512
#define IN_DIM  64
#define H       100
#define HP      128        // padded u (xw scratch stride)
#define JPS     13         // j-pairs per slice (4 slices: 52 pairs = 104 j)
#define HBUF    416        // 52 jp * 8 floats per h buffer

typedef unsigned long long u64t;

// scratch: [T][B][HP] floats = 134 MB (zero-init; pad cols never written)
__device__ float g_xw[(size_t)T_STEPS * BATCH * HP];

__device__ __forceinline__ void ffma2(u64t& d, u64t a, u64t b) {
    asm("fma.rn.f32x2 %0, %1, %2, %0;" : "+l"(d) : "l"(a), "l"(b));
}
__device__ __forceinline__ u64t pack2(float lo, float hi) {
    u64t r;
    asm("mov.b64 %0, {%1, %2};" : "=l"(r) : "f"(lo), "f"(hi));
    return r;
}
__device__ __forceinline__ void unpack2(float& lo, float& hi, u64t v) {
    asm("mov.b64 {%0, %1}, %2;" : "=f"(lo), "=f"(hi) : "l"(v));
}
__device__ __forceinline__ float sum2(u64t v) {
    float lo, hi;
    unpack2(lo, hi, v);
    return lo + hi;
}
// tanh via exp(2x): 2 MUFU + few FMA, abs err ~1e-7 with clamp.
__device__ __forceinline__ float fast_tanh(float x) {
    x = fminf(fmaxf(x, -15.0f), 15.0f);
    float e;
    asm("ex2.approx.f32 %0, %1;" : "=f"(e) : "f"(x * 2.885390081777927f));
    float r;
    asm("rcp.approx.f32 %0, %1;" : "=f"(r) : "f"(e + 1.0f));
    return (e - 1.0f) * r;
}

// ---------------------------------------------------------------------------
// Kernel 1: xw[t][b][u] = b1[u] + x[b][t][:] @ W1x[:][u]
// 8 rows/thread as f32x2 row-pairs; weights SMEM-replicated [d][u][2].
// ---------------------------------------------------------------------------
#define PC_THREADS 200

__global__ void __launch_bounds__(PC_THREADS) precompute_xw_kernel(
    const float* __restrict__ x,     // [B][T][D]
    const float* __restrict__ W1x,   // [D][H]
    const float* __restrict__ b1)    // [H]
{
    __shared__ __align__(16) float sWr[IN_DIM * H * 2];  // [d][u][2] replicated
    __shared__ __align__(16) float sxT[IN_DIM * 64];     // [d][row]

    const int t   = blockIdx.x;
    const int b0  = blockIdx.y * 64;
    const int tid = threadIdx.x;

    for (int i = tid; i < IN_DIM * H; i += PC_THREADS) {
        float w = W1x[i];
        sWr[2 * i] = w; sWr[2 * i + 1] = w;
    }
    for (int i = tid; i < 64 * IN_DIM; i += PC_THREADS) {
        int bl = i >> 6, d = i & 63;
        sxT[d * 64 + bl] =
            x[(size_t)(b0 + bl) * (T_STEPS * IN_DIM) + (size_t)t * IN_DIM + d];
    }
    __syncthreads();

    const int ug = tid >> 3;     // 0..24 -> u = 4*ug
    const int ro = tid & 7;      // rows ro*8 .. ro*8+7
    const int u  = ug * 4;

    u64t acc[4][4];
    #pragma unroll
    for (int ul = 0; ul < 4; ul++) {
        float b = b1[u + ul];
        #pragma unroll
        for (int rp = 0; rp < 4; rp++) acc[ul][rp] = pack2(b, b);
    }

    #pragma unroll 8
    for (int d = 0; d < IN_DIM; d++) {
        ulonglong2 x01 = *(const ulonglong2*)&sxT[d * 64 + ro * 8];
        ulonglong2 x23 = *(const ulonglong2*)&sxT[d * 64 + ro * 8 + 4];
        ulonglong2 wq0 = *(const ulonglong2*)&sWr[(d * H + u) * 2];
        ulonglong2 wq1 = *(const ulonglong2*)&sWr[(d * H + u) * 2 + 4];
        ffma2(acc[0][0], x01.x, wq0.x); ffma2(acc[0][1], x01.y, wq0.x);
        ffma2(acc[0][2], x23.x, wq0.x); ffma2(acc[0][3], x23.y, wq0.x);
        ffma2(acc[1][0], x01.x, wq0.y); ffma2(acc[1][1], x01.y, wq0.y);
        ffma2(acc[1][2], x23.x, wq0.y); ffma2(acc[1][3], x23.y, wq0.y);
        ffma2(acc[2][0], x01.x, wq1.x); ffma2(acc[2][1], x01.y, wq1.x);
        ffma2(acc[2][2], x23.x, wq1.x); ffma2(acc[2][3], x23.y, wq1.x);
        ffma2(acc[3][0], x01.x, wq1.y); ffma2(acc[3][1], x01.y, wq1.y);
        ffma2(acc[3][2], x23.x, wq1.y); ffma2(acc[3][3], x23.y, wq1.y);
    }

    #pragma unroll
    for (int rp = 0; rp < 4; rp++) {
        float l0, h0, l1, h1, l2, h2, l3, h3;
        unpack2(l0, h0, acc[0][rp]);
        unpack2(l1, h1, acc[1][rp]);
        unpack2(l2, h2, acc[2][rp]);
        unpack2(l3, h3, acc[3][rp]);
        int r0 = ro * 8 + rp * 2;
        size_t base = (size_t)t * (BATCH * HP) + (size_t)(b0 + r0) * HP + u;
        *(float4*)&g_xw[base]      = make_float4(l0, l1, l2, l3);
        *(float4*)&g_xw[base + HP] = make_float4(h0, h1, h2, h3);
    }
}

// ---------------------------------------------------------------------------
// Kernel 2: recurrence. 128 blocks x 4 batch rows, 512 threads (16 warps).
//   warp w: slice s = w&3 (13 j-pairs), u-group ug = w>>2
//   thread: u = ug*32 + lane (one hidden unit), partials for all 4 rows
// h loads: warp-uniform broadcasts. Weights in registers.
// scr[row][slice][u] partial exchange; warp of slice s finalizes row s.
// ---------------------------------------------------------------------------
__global__ void __launch_bounds__(512, 1) rnn_kernel(
    const float* __restrict__ W1h,  // [H][H]
    const float* __restrict__ W2x,  // [H][H]
    const float* __restrict__ W2h,  // [H][H]
    const float* __restrict__ b2,   // [H]
    const float* __restrict__ Wo,   // [H][1]
    const float* __restrict__ bo,   // [1]
    float* __restrict__ out)        // [512 + 51200 + 51200]
{
    __shared__ __align__(16) float sh1[2 * HBUF];   // [2][52][4][2]
    __shared__ __align__(16) float sh2[2 * HBUF];
    __shared__ __align__(16) float scr[4 * 4 * HP]; // [row][slice][u]
    __shared__ float sWo[HP];

    const int tid  = threadIdx.x;
    const int lane = tid & 31;
    const int w    = tid >> 5;           // 0..15
    const int s    = w & 3;              // slice / reduce-row
    const int ug   = w >> 2;             // 0..3
    const int u    = ug * 32 + lane;     // 0..127
    const int b0   = blockIdx.x * 4;
    const bool act = (u < H);

    // ---- weights into registers: packed f32x2 over j-pair, my slice ----
    u64t w1p[JPS], wxp[JPS], whp[JPS];
    #pragma unroll
    for (int jp = 0; jp < JPS; jp++) {
        const int j = s * (2 * JPS) + 2 * jp;   // 0..102
        float a0 = 0.f, a1 = 0.f, x0 = 0.f, x1 = 0.f, c0 = 0.f, c1 = 0.f;
        if (act) {
            if (j < H)     { a0 = W1h[j * H + u];       x0 = W2x[j * H + u];       c0 = W2h[j * H + u]; }
            if (j + 1 < H) { a1 = W1h[(j + 1) * H + u]; x1 = W2x[(j + 1) * H + u]; c1 = W2h[(j + 1) * H + u]; }
        }
        w1p[jp] = pack2(a0, a1);
        wxp[jp] = pack2(x0, x1);
        whp[jp] = pack2(c0, c1);
    }
    const float bias = act ? b2[u] : 0.f;
    if (tid < H) sWo[tid] = Wo[tid];
    for (int i = tid; i < 2 * HBUF; i += 512) { sh1[i] = 0.f; sh2[i] = 0.f; }
    __syncthreads();

    const int sbase = s * (JPS * 8);                  // my slice's j-range
    const int hpos  = (u >> 1) * 8 + s * 2 + (u & 1); // h store (row=s, unit u)

    // xw for (row=s, unit u): contiguous per warp
    const float* xwptr = g_xw + (size_t)(b0 + s) * HP + u;
    float xwc = *xwptr;

    for (int t = 0; t < T_STEPS; t++) {
        const int rb = (t & 1) * HBUF;
        const int wb = HBUF - rb;
        const float* h1r = sh1 + rb + sbase;
        const float* h1n = sh1 + wb + sbase;
        const float* h2r = sh2 + rb + sbase;

        float xwn = 0.f;
        if (t + 1 < T_STEPS)
            xwn = *(xwptr + (size_t)(t + 1) * (BATCH * HP));

        // ===== layer 1 partials: rows 0..3, my slice =====
        u64t a0 = 0, a1 = 0, a2 = 0, a3 = 0;
        #pragma unroll
        for (int jp = 0; jp < JPS; jp++) {
            ulonglong2 q01 = *(const ulonglong2*)&h1r[jp * 8];      // rows 0,1
            ulonglong2 q23 = *(const ulonglong2*)&h1r[jp * 8 + 4];  // rows 2,3
            ffma2(a0, q01.x, w1p[jp]);
            ffma2(a1, q01.y, w1p[jp]);
            ffma2(a2, q23.x, w1p[jp]);
            ffma2(a3, q23.y, w1p[jp]);
        }
        {
            float p0 = sum2(a0), p1 = sum2(a1), p2 = sum2(a2), p3 = sum2(a3);
            if (s != 0) scr[0 * 512 + s * HP + u] = p0;
            if (s != 1) scr[1 * 512 + s * HP + u] = p1;
            if (s != 2) scr[2 * 512 + s * HP + u] = p2;
            if (s != 3) scr[3 * 512 + s * HP + u] = p3;
            __syncthreads();
            float own = (s == 0) ? p0 : (s == 1) ? p1 : (s == 2) ? p2 : p3;
            #pragma unroll
            for (int sp = 0; sp < 4; sp++)
                if (sp != s) own += scr[s * 512 + sp * HP + u];
            float v = fast_tanh(own + xwc);
            if (act) sh1[wb + hpos] = v;
        }
        __syncthreads();   // h1_new visible; scr free

        // ===== layer 2 partials: h1_new @ W2x + h2_old @ W2h =====
        u64t c0 = 0, c1 = 0, c2 = 0, c3 = 0;
        #pragma unroll
        for (int jp = 0; jp < JPS; jp++) {
            ulonglong2 p01 = *(const ulonglong2*)&h1n[jp * 8];
            ulonglong2 p23 = *(const ulonglong2*)&h1n[jp * 8 + 4];
            ulonglong2 q01 = *(const ulonglong2*)&h2r[jp * 8];
            ulonglong2 q23 = *(const ulonglong2*)&h2r[jp * 8 + 4];
            ffma2(c0, p01.x, wxp[jp]); ffma2(c0, q01.x, whp[jp]);
            ffma2(c1, p01.y, wxp[jp]); ffma2(c1, q01.y, whp[jp]);
            ffma2(c2, p23.x, wxp[jp]); ffma2(c2, q23.x, whp[jp]);
            ffma2(c3, p23.y, wxp[jp]); ffma2(c3, q23.y, whp[jp]);
        }
        {
            float p0 = sum2(c0), p1 = sum2(c1), p2 = sum2(c2), p3 = sum2(c3);
            if (s != 0) scr[0 * 512 + s * HP + u] = p0;
            if (s != 1) scr[1 * 512 + s * HP + u] = p1;
            if (s != 2) scr[2 * 512 + s * HP + u] = p2;
            if (s != 3) scr[3 * 512 + s * HP + u] = p3;
            __syncthreads();
            float own = (s == 0) ? p0 : (s == 1) ? p1 : (s == 2) ? p2 : p3;
            #pragma unroll
            for (int sp = 0; sp < 4; sp++)
                if (sp != s) own += scr[s * 512 + sp * HP + u];
            float v = fast_tanh(own + bias);
            if (act) sh2[wb + hpos] = v;
        }
        __syncthreads();   // h2_new visible; old buffers free

        xwc = xwn;
    }

    // ---- epilogue: final state in buffer 0 (T even) ----
    for (int i = tid; i < 4 * H; i += 512) {
        int r = i / H;
        int uu = i - r * H;
        int pos = (uu >> 1) * 8 + r * 2 + (uu & 1);
        out[512 + (size_t)(b0 + r) * H + uu]         = sh1[pos];
        out[512 + 51200 + (size_t)(b0 + r) * H + uu] = sh2[pos];
    }
    if (tid < 4) {
        float sacc = bo[0];
        for (int j = 0; j < H; j++)
            sacc += sh2[(j >> 1) * 8 + tid * 2 + (j & 1)] * sWo[j];
        out[b0 + tid] = sacc;
    }
}

// ---------------------------------------------------------------------------
extern "C" void kernel_launch(void* const* d_in, const int* in_sizes, int n_in,
                              void* d_out, int out_size)
{
    const float* x   = (const float*)d_in[0];
    const float* W1x = (const float*)d_in[1];
    const float* W1h = (const float*)d_in[2];
    const float* b1  = (const float*)d_in[3];
    const float* W2x = (const float*)d_in[4];
    const float* W2h = (const float*)d_in[5];
    const float* b2  = (const float*)d_in[6];
    const float* Wo  = (const float*)d_in[7];
    const float* bo  = (const float*)d_in[8];
    float* out = (float*)d_out;

    precompute_xw_kernel<<<dim3(T_STEPS, BATCH / 64), PC_THREADS>>>(x, W1x, b1);
    rnn_kernel<<<BATCH / 4, 512>>>(W1h, W2x, W2h, b2, Wo, bo, out);
}

// round 8
// speedup vs baseline: 1.1363x; 1.1363x over previous
#include <cuda_runtime.h>
#include <cuda_bf16.h>
#include <cstddef>

// ---------------------------------------------------------------------------
// DRNN: 2-layer SimpleRNN (tanh), B=512, T=512, D=64, H=100.
//   h1_t = tanh(x_t @ W1x + h1_{t-1} @ W1h + b1)
//   h2_t = tanh(h1_t @ W2x + h2_{t-1} @ W2h + b2)
//   out  = h2_T @ Wo + bo
// d_out: out[512] | h1_T[512*100] | h2_T[512*100]
//
// R7 lesson: LDS-wf and FFMA2 per step are invariant across slicings; RF is
// the wall (weights ~40k/64k regs per SM). R4's 256-thread/2-slice mapping
// measured fastest (767us) -> keep it exactly; bank tanh-approx + smaller
// xw stride (HP=104) + leaner precompute (no weight replication).
// ---------------------------------------------------------------------------

#define T_STEPS 512
#define BATCH   512
#define IN_DIM  64
#define H       100
#define HP      104   // xw scratch stride (was 128)
#define JPH     25    // j-pairs per half (half covers 50 j values)

typedef unsigned long long u64t;

// scratch: [T][B][HP] floats = 109 MB (zero-init; pad cols 100..103 unread)
__device__ float g_xw[(size_t)T_STEPS * BATCH * HP];

__device__ __forceinline__ void ffma2(u64t& d, u64t a, u64t b) {
    asm("fma.rn.f32x2 %0, %1, %2, %0;" : "+l"(d) : "l"(a), "l"(b));
}
__device__ __forceinline__ u64t pack2(float lo, float hi) {
    u64t r;
    asm("mov.b64 %0, {%1, %2};" : "=l"(r) : "f"(lo), "f"(hi));
    return r;
}
__device__ __forceinline__ void unpack2(float& lo, float& hi, u64t v) {
    asm("mov.b64 {%0, %1}, %2;" : "=f"(lo), "=f"(hi) : "l"(v));
}
__device__ __forceinline__ float sum2(u64t v) {
    float lo, hi;
    unpack2(lo, hi, v);
    return lo + hi;
}
// tanh via exp(2x): 2 MUFU + few FMA, abs err ~1e-7 with clamp.
// (validated R5/R7: rel_err 4.1e-7)
__device__ __forceinline__ float fast_tanh(float x) {
    x = fminf(fmaxf(x, -15.0f), 15.0f);
    float e;
    asm("ex2.approx.f32 %0, %1;" : "=f"(e) : "f"(x * 2.885390081777927f));
    float r;
    asm("rcp.approx.f32 %0, %1;" : "=f"(r) : "f"(e + 1.0f));
    return (e - 1.0f) * r;
}

// ---------------------------------------------------------------------------
// Kernel 1: xw[t][b][u] = b1[u] + x[b][t][:] @ W1x[:][u]
// grid (512 t, 8 chunks of 64 rows), 200 threads: (ug 0..24) x (ro 0..7).
// 8 rows/thread as f32x2 row-pairs. Weights plain [d][u] (no replication):
// one LDS.128 per d + 4 ALU packs replaces 2 LDS.128. SMEM 42KB.
// ---------------------------------------------------------------------------
#define PC_THREADS 200

__global__ void __launch_bounds__(PC_THREADS) precompute_xw_kernel(
    const float* __restrict__ x,     // [B][T][D]
    const float* __restrict__ W1x,   // [D][H]
    const float* __restrict__ b1)    // [H]
{
    __shared__ __align__(16) float sW[IN_DIM * H];   // [d][u] 25.6KB
    __shared__ __align__(16) float sxT[IN_DIM * 64]; // [d][row] 16KB

    const int t   = blockIdx.x;
    const int b0  = blockIdx.y * 64;
    const int tid = threadIdx.x;

    for (int i = tid; i < IN_DIM * H; i += PC_THREADS) sW[i] = W1x[i];
    for (int i = tid; i < 64 * IN_DIM; i += PC_THREADS) {
        int bl = i >> 6, d = i & 63;
        sxT[d * 64 + bl] =
            x[(size_t)(b0 + bl) * (T_STEPS * IN_DIM) + (size_t)t * IN_DIM + d];
    }
    __syncthreads();

    const int ug = tid >> 3;     // 0..24 -> u = 4*ug
    const int ro = tid & 7;      // rows ro*8 .. ro*8+7
    const int u  = ug * 4;

    u64t acc[4][4];              // [u-local][row-pair]
    #pragma unroll
    for (int ul = 0; ul < 4; ul++) {
        float b = b1[u + ul];
        #pragma unroll
        for (int rp = 0; rp < 4; rp++) acc[ul][rp] = pack2(b, b);
    }

    #pragma unroll 8
    for (int d = 0; d < IN_DIM; d++) {
        ulonglong2 x01 = *(const ulonglong2*)&sxT[d * 64 + ro * 8];      // rows +0..3
        ulonglong2 x23 = *(const ulonglong2*)&sxT[d * 64 + ro * 8 + 4];  // rows +4..7
        // byte offset (d*100 + 4*ug)*4 = 400d + 16ug -> 16B aligned
        float4 w = *(const float4*)&sW[d * H + u];
        u64t w0 = pack2(w.x, w.x);   // ALU-pipe movs, overlap with FMA
        u64t w1 = pack2(w.y, w.y);
        u64t w2 = pack2(w.z, w.z);
        u64t w3 = pack2(w.w, w.w);
        ffma2(acc[0][0], x01.x, w0); ffma2(acc[0][1], x01.y, w0);
        ffma2(acc[0][2], x23.x, w0); ffma2(acc[0][3], x23.y, w0);
        ffma2(acc[1][0], x01.x, w1); ffma2(acc[1][1], x01.y, w1);
        ffma2(acc[1][2], x23.x, w1); ffma2(acc[1][3], x23.y, w1);
        ffma2(acc[2][0], x01.x, w2); ffma2(acc[2][1], x01.y, w2);
        ffma2(acc[2][2], x23.x, w2); ffma2(acc[2][3], x23.y, w2);
        ffma2(acc[3][0], x01.x, w3); ffma2(acc[3][1], x01.y, w3);
        ffma2(acc[3][2], x23.x, w3); ffma2(acc[3][3], x23.y, w3);
    }

    #pragma unroll
    for (int rp = 0; rp < 4; rp++) {
        float l0, h0, l1, h1, l2, h2, l3, h3;
        unpack2(l0, h0, acc[0][rp]);
        unpack2(l1, h1, acc[1][rp]);
        unpack2(l2, h2, acc[2][rp]);
        unpack2(l3, h3, acc[3][rp]);
        int r0 = ro * 8 + rp * 2;
        // (b*HP + u): b*104 + 4k -> both div 4 -> 16B aligned
        size_t base = (size_t)t * (BATCH * HP) + (size_t)(b0 + r0) * HP + u;
        *(float4*)&g_xw[base]      = make_float4(l0, l1, l2, l3);
        *(float4*)&g_xw[base + HP] = make_float4(h0, h1, h2, h3);
    }
}

// ---------------------------------------------------------------------------
// Kernel 2: recurrence — R4 structure (measured best). 128 blocks x 4 rows,
// 256 threads (8 warps): u = tid&127, half = tid>>7 (j-range 50 per half).
// Weights in registers (75 packed f32x2/thread). h state SMEM [jp][row][2],
// double buffered. Per layer: partials -> scr exchange -> reduce + tanh.
// ---------------------------------------------------------------------------
#define SM_H1  0      // [2][400]
#define SM_H2  800    // [2][400]
#define SM_SCR 1600   // [2][128][2] = 512
#define SM_WO  2112   // [128]
#define SM_FLOATS 2240

__global__ void __launch_bounds__(256, 1) rnn_kernel(
    const float* __restrict__ W1h,  // [H][H]
    const float* __restrict__ W2x,  // [H][H]
    const float* __restrict__ W2h,  // [H][H]
    const float* __restrict__ b2,   // [H]
    const float* __restrict__ Wo,   // [H][1]
    const float* __restrict__ bo,   // [1]
    float* __restrict__ out)        // [512 + 51200 + 51200]
{
    __shared__ __align__(16) float sm[SM_FLOATS];
    float* sh1 = sm + SM_H1;
    float* sh2 = sm + SM_H2;
    float* scr = sm + SM_SCR;
    float* sWo = sm + SM_WO;

    const int tid  = threadIdx.x;
    const int u    = tid & 127;
    const int hf   = tid >> 7;          // 0 or 1
    const int b0   = blockIdx.x * 4;
    const bool act = (u < H);

    // ---- weight slices into registers (packed f32x2 over j-pairs) ----
    u64t w1p[JPH], wxp[JPH], whp[JPH];
    #pragma unroll
    for (int jp = 0; jp < JPH; jp++) {
        int j = hf * 50 + 2 * jp;
        float a0 = 0.f, a1 = 0.f, x0 = 0.f, x1 = 0.f, c0 = 0.f, c1 = 0.f;
        if (act) {
            a0 = W1h[j * H + u]; a1 = W1h[(j + 1) * H + u];
            x0 = W2x[j * H + u]; x1 = W2x[(j + 1) * H + u];
            c0 = W2h[j * H + u]; c1 = W2h[(j + 1) * H + u];
        }
        w1p[jp] = pack2(a0, a1);
        wxp[jp] = pack2(x0, x1);
        whp[jp] = pack2(c0, c1);
    }
    const float bb = (act && hf == 0) ? b2[u] : 0.0f;  // bias only in half0
    if (tid < H) sWo[tid] = Wo[tid];
    for (int i = tid; i < 1600; i += 256) sm[i] = 0.0f;  // zero both h bufs
    __syncthreads();

    const int hbase = (u >> 1) * 8 + (u & 1);  // h write base for unit u
    const int hoff  = hf * 200;                // this half's j-offset in h buf

    // prefetch xw for t=0 (half0 only; half0 carries xw into its partials)
    float xw0 = 0.f, xw1 = 0.f, xw2 = 0.f, xw3 = 0.f;
    if (hf == 0 && act) {
        size_t base = (size_t)b0 * HP + u;
        xw0 = g_xw[base];
        xw1 = g_xw[base + HP];
        xw2 = g_xw[base + 2 * HP];
        xw3 = g_xw[base + 3 * HP];
    }

    for (int t = 0; t < T_STEPS; t++) {
        const int rb = (t & 1) * 400;        // read buffer
        const int wb = 400 - rb;             // write buffer
        const float* h1r = sh1 + rb;
        float*       h1w = sh1 + wb;
        const float* h2r = sh2 + rb;
        float*       h2w = sh2 + wb;

        // software-pipelined prefetch of next timestep's xw
        float nx0 = 0.f, nx1 = 0.f, nx2 = 0.f, nx3 = 0.f;
        if (hf == 0 && act && (t + 1 < T_STEPS)) {
            size_t base = (size_t)(t + 1) * (BATCH * HP) + (size_t)b0 * HP + u;
            nx0 = g_xw[base];
            nx1 = g_xw[base + HP];
            nx2 = g_xw[base + 2 * HP];
            nx3 = g_xw[base + 3 * HP];
        }

        // ---- layer 1 partials: xw(+half0) + sum_{j in my half} h1_old*W1h ----
        u64t a0 = pack2(xw0, 0.f), a1 = pack2(xw1, 0.f);
        u64t a2 = pack2(xw2, 0.f), a3 = pack2(xw3, 0.f);
        #pragma unroll
        for (int jp = 0; jp < JPH; jp++) {
            ulonglong2 q01 = *(const ulonglong2*)&h1r[hoff + jp * 8];      // rows 0,1
            ulonglong2 q23 = *(const ulonglong2*)&h1r[hoff + jp * 8 + 4];  // rows 2,3
            ffma2(a0, q01.x, w1p[jp]);
            ffma2(a1, q01.y, w1p[jp]);
            ffma2(a2, q23.x, w1p[jp]);
            ffma2(a3, q23.y, w1p[jp]);
        }
        {
            float s0 = sum2(a0), s1 = sum2(a1), s2 = sum2(a2), s3 = sum2(a3);
            // hand partner its 2 rows
            float p0 = hf ? s0 : s2;
            float p1 = hf ? s1 : s3;
            *(float2*)&scr[(hf * 128 + u) * 2] = make_float2(p0, p1);
            __syncthreads();
            float2 o = *(const float2*)&scr[((1 - hf) * 128 + u) * 2];
            float m0 = hf ? s2 : s0;
            float m1 = hf ? s3 : s1;
            float v0 = fast_tanh(m0 + o.x);
            float v1 = fast_tanh(m1 + o.y);
            if (act) {
                h1w[hbase + (2 * hf) * 2]     = v0;   // row 2*hf
                h1w[hbase + (2 * hf + 1) * 2] = v1;   // row 2*hf+1
            }
        }
        __syncthreads();   // h1_new visible; h1_old reads done

        // ---- layer 2 partials: b2(+half0) + h1_new@W2x + h2_old@W2h ----
        u64t c0 = pack2(bb, 0.f), c1 = pack2(bb, 0.f);
        u64t c2 = pack2(bb, 0.f), c3 = pack2(bb, 0.f);
        #pragma unroll
        for (int jp = 0; jp < JPH; jp++) {
            ulonglong2 p01 = *(const ulonglong2*)&h1w[hoff + jp * 8];
            ulonglong2 p23 = *(const ulonglong2*)&h1w[hoff + jp * 8 + 4];
            ulonglong2 q01 = *(const ulonglong2*)&h2r[hoff + jp * 8];
            ulonglong2 q23 = *(const ulonglong2*)&h2r[hoff + jp * 8 + 4];
            ffma2(c0, p01.x, wxp[jp]); ffma2(c0, q01.x, whp[jp]);
            ffma2(c1, p01.y, wxp[jp]); ffma2(c1, q01.y, whp[jp]);
            ffma2(c2, p23.x, wxp[jp]); ffma2(c2, q23.x, whp[jp]);
            ffma2(c3, p23.y, wxp[jp]); ffma2(c3, q23.y, whp[jp]);
        }
        {
            float s0 = sum2(c0), s1 = sum2(c1), s2 = sum2(c2), s3 = sum2(c3);
            float p0 = hf ? s0 : s2;
            float p1 = hf ? s1 : s3;
            *(float2*)&scr[(hf * 128 + u) * 2] = make_float2(p0, p1);
            __syncthreads();
            float2 o = *(const float2*)&scr[((1 - hf) * 128 + u) * 2];
            float m0 = hf ? s2 : s0;
            float m1 = hf ? s3 : s1;
            float g0 = fast_tanh(m0 + o.x);
            float g1 = fast_tanh(m1 + o.y);
            if (act) {
                h2w[hbase + (2 * hf) * 2]     = g0;
                h2w[hbase + (2 * hf + 1) * 2] = g1;
            }
        }
        __syncthreads();   // h2_new visible; old buffers free

        xw0 = nx0; xw1 = nx1; xw2 = nx2; xw3 = nx3;
    }

    // ---- epilogue: final state lives in buffer 0 (T=512 even) ----
    const float* h1f = sh1;
    const float* h2f = sh2;
    if (act && hf == 0) {
        #pragma unroll
        for (int r = 0; r < 4; r++) {
            float hv1 = h1f[(u >> 1) * 8 + r * 2 + (u & 1)];
            float hv2 = h2f[(u >> 1) * 8 + r * 2 + (u & 1)];
            out[512 + (size_t)(b0 + r) * H + u]         = hv1;
            out[512 + 51200 + (size_t)(b0 + r) * H + u] = hv2;
        }
    }
    if (tid < 4) {
        float s = bo[0];
        for (int j = 0; j < H; j++)
            s += h2f[(j >> 1) * 8 + tid * 2 + (j & 1)] * sWo[j];
        out[b0 + tid] = s;
    }
}

// ---------------------------------------------------------------------------
extern "C" void kernel_launch(void* const* d_in, const int* in_sizes, int n_in,
                              void* d_out, int out_size)
{
    const float* x   = (const float*)d_in[0];
    const float* W1x = (const float*)d_in[1];
    const float* W1h = (const float*)d_in[2];
    const float* b1  = (const float*)d_in[3];
    const float* W2x = (const float*)d_in[4];
    const float* W2h = (const float*)d_in[5];
    const float* b2  = (const float*)d_in[6];
    const float* Wo  = (const float*)d_in[7];
    const float* bo  = (const float*)d_in[8];
    float* out = (float*)d_out;

    precompute_xw_kernel<<<dim3(T_STEPS, BATCH / 64), PC_THREADS>>>(x, W1x, b1);
    rnn_kernel<<<BATCH / 4, 256>>>(W1h, W2x, W2h, b2, Wo, bo, out);
}